// round 2
// baseline (speedup 1.0000x reference)
#include <cuda_runtime.h>
#include <math.h>

#define BB 16
#define CC 512
#define TT 1024
#define NG 32
#define CPG 16
#define NH 8
#define DH 64
#define CO (3*CC)

// Scratch (device globals; no allocations allowed)
__device__ float g_xn[(size_t)BB*CC*TT];     // groupnorm output
__device__ float g_qkv[(size_t)BB*CO*TT];    // qkv projection output
__device__ float g_attn[(size_t)BB*CC*TT];   // attention output

// ---------------------------------------------------------------------------
// GroupNorm: one block per (b, group). 16 ch x 1024 t = 16384 elems per group.
// ---------------------------------------------------------------------------
__global__ __launch_bounds__(256)
void gn_kernel(const float* __restrict__ x,
               const float* __restrict__ scale,
               const float* __restrict__ bias)
{
    int b = blockIdx.x / NG;
    int g = blockIdx.x % NG;
    const float* xp = x + ((size_t)b*CC + (size_t)g*CPG) * TT;
    float* yp = g_xn + ((size_t)b*CC + (size_t)g*CPG) * TT;
    int tid = threadIdx.x;

    float s = 0.f, ss = 0.f;
    for (int i = tid; i < CPG*TT; i += 256) {
        float v = xp[i];
        s += v;
        ss += v*v;
    }
    __shared__ float rs[256], rss[256];
    rs[tid] = s; rss[tid] = ss;
    __syncthreads();
    for (int o = 128; o > 0; o >>= 1) {
        if (tid < o) { rs[tid] += rs[tid+o]; rss[tid] += rss[tid+o]; }
        __syncthreads();
    }
    const float inv_n = 1.0f / (CPG*TT);
    float mean = rs[0] * inv_n;
    float var  = rss[0] * inv_n - mean*mean;
    float rstd = rsqrtf(var + 1e-5f);

    for (int i = tid; i < CPG*TT; i += 256) {
        int c = g*CPG + (i >> 10);   // i / TT
        yp[i] = (xp[i] - mean) * rstd * scale[c] + bias[c];
    }
}

// ---------------------------------------------------------------------------
// Batched SGEMM: C[batch] = A (MxK, shared) @ B[batch] (KxN) + bias (+ resid)
// 64x64 tile, K-tile 16, 256 threads, 4x4 microtile per thread.
// grid: (N/64, M/64, batch)
// ---------------------------------------------------------------------------
__global__ __launch_bounds__(256)
void gemm_kernel(const float* __restrict__ A,
                 const float* __restrict__ Bm,
                 float* __restrict__ Cm,
                 const float* __restrict__ bias,
                 const float* __restrict__ resid,
                 int M, int N, int K)
{
    int batch = blockIdx.z;
    const float* Bp = Bm + (size_t)batch * K * N;
    float*       Cp = Cm + (size_t)batch * M * N;
    const float* Rp = resid ? (resid + (size_t)batch * M * N) : nullptr;
    int m0 = blockIdx.y * 64;
    int n0 = blockIdx.x * 64;

    __shared__ float sA[16][68];   // [k][m], padded for conflict-free stores
    __shared__ float sB[16][64];   // [k][n]

    int tid = threadIdx.x;
    int ty = tid >> 4;   // 0..15  -> rows (m)
    int tx = tid & 15;   // 0..15  -> cols (n)

    float acc[4][4];
    #pragma unroll
    for (int i = 0; i < 4; i++)
        #pragma unroll
        for (int j = 0; j < 4; j++) acc[i][j] = 0.f;

    // A-load mapping: thread t loads one float4 along k: m = t>>2, kq = t&3
    int a_m = tid >> 2;
    int a_k4 = (tid & 3) * 4;
    // B-load mapping: thread t loads one float4 along n: k = t>>4, nq = t&15
    int b_k = tid >> 4;
    int b_n4 = (tid & 15) * 4;

    for (int k0 = 0; k0 < K; k0 += 16) {
        float4 av = *(const float4*)&A[(size_t)(m0 + a_m) * K + k0 + a_k4];
        sA[a_k4 + 0][a_m] = av.x;
        sA[a_k4 + 1][a_m] = av.y;
        sA[a_k4 + 2][a_m] = av.z;
        sA[a_k4 + 3][a_m] = av.w;
        float4 bv = *(const float4*)&Bp[(size_t)(k0 + b_k) * N + n0 + b_n4];
        *(float4*)&sB[b_k][b_n4] = bv;
        __syncthreads();

        #pragma unroll
        for (int kk = 0; kk < 16; kk++) {
            float4 a = *(const float4*)&sA[kk][ty*4];
            float4 b = *(const float4*)&sB[kk][tx*4];
            float ar[4] = {a.x, a.y, a.z, a.w};
            float br[4] = {b.x, b.y, b.z, b.w};
            #pragma unroll
            for (int i = 0; i < 4; i++)
                #pragma unroll
                for (int j = 0; j < 4; j++)
                    acc[i][j] += ar[i] * br[j];
        }
        __syncthreads();
    }

    #pragma unroll
    for (int i = 0; i < 4; i++) {
        int m = m0 + ty*4 + i;
        float bv = bias ? bias[m] : 0.f;
        float4 out;
        float v[4];
        #pragma unroll
        for (int j = 0; j < 4; j++) {
            v[j] = acc[i][j] + bv;
        }
        size_t base = (size_t)m * N + n0 + tx*4;
        if (Rp) {
            float4 r = *(const float4*)&Rp[base];
            v[0] += r.x; v[1] += r.y; v[2] += r.z; v[3] += r.w;
        }
        out.x = v[0]; out.y = v[1]; out.z = v[2]; out.w = v[3];
        *(float4*)&Cp[base] = out;
    }
}

// ---------------------------------------------------------------------------
// Flash attention: one block per (bh, q-tile of 64). 256 threads.
// Q/K/V laid out (dh, t) in g_qkv; head h of batch b at channel h*192 (+64/+128).
// Online softmax over 16 s-tiles of 64.
// ---------------------------------------------------------------------------
__global__ __launch_bounds__(256)
void attn_kernel()
{
    int bh = blockIdx.y;
    int b = bh >> 3;
    int h = bh & 7;
    int qt0 = blockIdx.x * 64;

    const float* qbase = g_qkv + ((size_t)b*CO + (size_t)h*192) * TT;
    const float* kbase = qbase + (size_t)64 * TT;
    const float* vbase = qbase + (size_t)128 * TT;

    __shared__ float sQ[64][64];    // [d][tq], pre-scaled
    __shared__ float sKP[64][64];   // [d][ts] for K, reused as [tq][ts] for P
    __shared__ float sV[64][64];    // [d][ts]

    int tid = threadIdx.x;
    int ty = tid >> 4;   // row group (tq)
    int tx = tid & 15;   // col group (ts / d)

    const float qscale = 0.125f;    // 1/sqrt(64) folded into Q
    for (int i = tid; i < 4096; i += 256) {
        int d = i >> 6, j = i & 63;
        sQ[d][j] = qbase[(size_t)d * TT + qt0 + j] * qscale;
    }

    float m[4], l[4], o[4][4];
    #pragma unroll
    for (int i = 0; i < 4; i++) {
        m[i] = -1e30f; l[i] = 0.f;
        #pragma unroll
        for (int j = 0; j < 4; j++) o[i][j] = 0.f;
    }

    for (int s0 = 0; s0 < TT; s0 += 64) {
        __syncthreads();   // prev-iter P/V reads done (and first-iter Q store ordering)
        for (int i = tid; i < 4096; i += 256) {
            int d = i >> 6, j = i & 63;
            sKP[d][j] = kbase[(size_t)d * TT + s0 + j];
            sV[d][j]  = vbase[(size_t)d * TT + s0 + j];
        }
        __syncthreads();

        // S = Q^T K (64x64), thread computes 4x4
        float sc[4][4];
        #pragma unroll
        for (int i = 0; i < 4; i++)
            #pragma unroll
            for (int j = 0; j < 4; j++) sc[i][j] = 0.f;

        #pragma unroll
        for (int d = 0; d < 64; d++) {
            float4 a = *(const float4*)&sQ[d][ty*4];
            float4 bq = *(const float4*)&sKP[d][tx*4];
            float ar[4] = {a.x, a.y, a.z, a.w};
            float br[4] = {bq.x, bq.y, bq.z, bq.w};
            #pragma unroll
            for (int i = 0; i < 4; i++)
                #pragma unroll
                for (int j = 0; j < 4; j++)
                    sc[i][j] += ar[i] * br[j];
        }

        // Row max (reduce over 16 threads sharing rows: consecutive lanes)
        float rm[4], p[4][4], rsum[4];
        #pragma unroll
        for (int i = 0; i < 4; i++) {
            rm[i] = fmaxf(fmaxf(sc[i][0], sc[i][1]), fmaxf(sc[i][2], sc[i][3]));
        }
        #pragma unroll
        for (int off = 1; off < 16; off <<= 1) {
            #pragma unroll
            for (int i = 0; i < 4; i++)
                rm[i] = fmaxf(rm[i], __shfl_xor_sync(0xffffffffu, rm[i], off));
        }
        #pragma unroll
        for (int i = 0; i < 4; i++) {
            float mn = fmaxf(m[i], rm[i]);
            float corr = __expf(m[i] - mn);
            float rs = 0.f;
            #pragma unroll
            for (int j = 0; j < 4; j++) {
                p[i][j] = __expf(sc[i][j] - mn);
                rs += p[i][j];
            }
            rsum[i] = rs;
            m[i] = mn;
            l[i] = l[i] * corr;
            #pragma unroll
            for (int j = 0; j < 4; j++) o[i][j] *= corr;
        }
        #pragma unroll
        for (int off = 1; off < 16; off <<= 1) {
            #pragma unroll
            for (int i = 0; i < 4; i++)
                rsum[i] += __shfl_xor_sync(0xffffffffu, rsum[i], off);
        }
        #pragma unroll
        for (int i = 0; i < 4; i++) l[i] += rsum[i];

        __syncthreads();  // everyone done reading K before overwriting with P
        #pragma unroll
        for (int i = 0; i < 4; i++) {
            float4 pv;
            pv.x = p[i][0]; pv.y = p[i][1]; pv.z = p[i][2]; pv.w = p[i][3];
            *(float4*)&sKP[ty*4 + i][tx*4] = pv;
        }
        __syncthreads();

        // O[tq][d] += P[tq][s] * V[d][s]; thread owns tq = 4ty+i, d = 4tx+j
        #pragma unroll
        for (int s = 0; s < 64; s += 4) {
            float4 pv[4], vv[4];
            #pragma unroll
            for (int i = 0; i < 4; i++) pv[i] = *(const float4*)&sKP[ty*4 + i][s];
            #pragma unroll
            for (int j = 0; j < 4; j++) vv[j] = *(const float4*)&sV[tx*4 + j][s];
            #pragma unroll
            for (int i = 0; i < 4; i++) {
                #pragma unroll
                for (int j = 0; j < 4; j++) {
                    o[i][j] += pv[i].x * vv[j].x + pv[i].y * vv[j].y
                             + pv[i].z * vv[j].z + pv[i].w * vv[j].w;
                }
            }
        }
    }

    // Epilogue: normalize and write attn[b][h*64 + d][tq]
    #pragma unroll
    for (int i = 0; i < 4; i++) {
        float inv = 1.0f / l[i];
        int tq = qt0 + ty*4 + i;
        #pragma unroll
        for (int j = 0; j < 4; j++) {
            int c = h*64 + tx*4 + j;
            g_attn[((size_t)b*CC + c) * TT + tq] = o[i][j] * inv;
        }
    }
}

// ---------------------------------------------------------------------------
// Launch
// ---------------------------------------------------------------------------
extern "C" void kernel_launch(void* const* d_in, const int* in_sizes, int n_in,
                              void* d_out, int out_size)
{
    const float* x        = (const float*)d_in[0];
    const float* gn_scale = (const float*)d_in[1];
    const float* gn_bias  = (const float*)d_in[2];
    const float* w_qkv    = (const float*)d_in[3];
    const float* b_qkv    = (const float*)d_in[4];
    const float* w_proj   = (const float*)d_in[5];
    const float* b_proj   = (const float*)d_in[6];
    float* out = (float*)d_out;

    float* xn_ptr;   cudaGetSymbolAddress((void**)&xn_ptr,   g_xn);
    float* qkv_ptr;  cudaGetSymbolAddress((void**)&qkv_ptr,  g_qkv);
    float* attn_ptr; cudaGetSymbolAddress((void**)&attn_ptr, g_attn);

    // 1) GroupNorm
    gn_kernel<<<BB*NG, 256>>>(x, gn_scale, gn_bias);

    // 2) QKV: per batch (1536x512) @ (512x1024)
    {
        dim3 grid(TT/64, CO/64, BB);
        gemm_kernel<<<grid, 256>>>(w_qkv, xn_ptr, qkv_ptr, b_qkv, nullptr,
                                   CO, TT, CC);
    }

    // 3) Attention (flash, online softmax)
    {
        dim3 grid(TT/64, BB*NH);
        attn_kernel<<<grid, 256>>>();
    }

    // 4) Proj + bias + residual
    {
        dim3 grid(TT/64, CC/64, BB);
        gemm_kernel<<<grid, 256>>>(w_proj, attn_ptr, out, b_proj, x,
                                   CC, TT, CC);
    }
}

// round 5
// speedup vs baseline: 10.4976x; 10.4976x over previous
#include <cuda_runtime.h>
#include <cuda_fp16.h>
#include <math.h>
#include <stdint.h>

#define BB 16
#define CC 512
#define TT 1024
#define NG 32
#define CPG 16
#define NH 8
#define DH 64
#define CO (3*CC)

// Scratch (device globals; no allocations allowed)
__device__ __half g_xn_h[(size_t)BB*CC*TT];    // groupnorm output (fp16)
__device__ __half g_qkv_h[(size_t)BB*CO*TT];   // qkv projection output (fp16)
__device__ __half g_attn_h[(size_t)BB*CC*TT];  // attention output (fp16)
__device__ __half g_wqkv_h[(size_t)CO*CC];     // fp16 weights
__device__ __half g_wproj_h[(size_t)CC*CC];

// ---------------------------------------------------------------------------
// helpers: ldmatrix + mma.sync (base sm_103 — no tcgen05 on this PTX target)
// ---------------------------------------------------------------------------
__device__ __forceinline__ uint32_t smem_u32(const void* p) {
    return (uint32_t)__cvta_generic_to_shared(p);
}
__device__ __forceinline__ void ldsm4(uint32_t* r, uint32_t a) {
    asm volatile("ldmatrix.sync.aligned.m8n8.x4.shared.b16 {%0,%1,%2,%3}, [%4];"
                 : "=r"(r[0]), "=r"(r[1]), "=r"(r[2]), "=r"(r[3]) : "r"(a));
}
__device__ __forceinline__ void ldsm4t(uint32_t* r, uint32_t a) {
    asm volatile("ldmatrix.sync.aligned.m8n8.x4.trans.shared.b16 {%0,%1,%2,%3}, [%4];"
                 : "=r"(r[0]), "=r"(r[1]), "=r"(r[2]), "=r"(r[3]) : "r"(a));
}
__device__ __forceinline__ void mma16816(float* c, const uint32_t* a, const uint32_t* b) {
    asm volatile("mma.sync.aligned.m16n8k16.row.col.f32.f16.f16.f32 "
                 "{%0,%1,%2,%3}, {%4,%5,%6,%7}, {%8,%9}, {%0,%1,%2,%3};"
                 : "+f"(c[0]), "+f"(c[1]), "+f"(c[2]), "+f"(c[3])
                 : "r"(a[0]), "r"(a[1]), "r"(a[2]), "r"(a[3]),
                   "r"(b[0]), "r"(b[1]));
}
__device__ __forceinline__ uint32_t packh2(float x, float y) {
    __half2 h = __floats2half2_rn(x, y);
    return *(uint32_t*)&h;
}

// ---------------------------------------------------------------------------
// fp32 -> fp16 conversion (weights)
// ---------------------------------------------------------------------------
__global__ void tohalf_kernel(const float* __restrict__ a, __half* __restrict__ b, int n)
{
    int i = blockIdx.x * 256 + threadIdx.x;
    if (i < n) b[i] = __float2half(a[i]);
}

// ---------------------------------------------------------------------------
// GroupNorm: one block per (b, group); fp16 output.
// ---------------------------------------------------------------------------
__global__ __launch_bounds__(256)
void gn_kernel(const float* __restrict__ x,
               const float* __restrict__ scale,
               const float* __restrict__ bias)
{
    int b = blockIdx.x / NG;
    int g = blockIdx.x % NG;
    const float* xp = x + ((size_t)b*CC + (size_t)g*CPG) * TT;
    __half* yp = g_xn_h + ((size_t)b*CC + (size_t)g*CPG) * TT;
    int tid = threadIdx.x;

    float s = 0.f, ss = 0.f;
    for (int i = tid; i < CPG*TT; i += 256) {
        float v = xp[i];
        s += v; ss += v*v;
    }
    __shared__ float rs[256], rss[256];
    rs[tid] = s; rss[tid] = ss;
    __syncthreads();
    for (int o = 128; o > 0; o >>= 1) {
        if (tid < o) { rs[tid] += rs[tid+o]; rss[tid] += rss[tid+o]; }
        __syncthreads();
    }
    const float inv_n = 1.0f / (CPG*TT);
    float mean = rs[0] * inv_n;
    float var  = rss[0] * inv_n - mean*mean;
    float rstd = rsqrtf(var + 1e-5f);

    for (int i = tid; i < CPG*TT; i += 256) {
        int c = g*CPG + (i >> 10);
        yp[i] = __float2half((xp[i] - mean) * rstd * scale[c] + bias[c]);
    }
}

// ---------------------------------------------------------------------------
// HMMA GEMM: C[b] = A(MxK fp16, shared) @ B[b](K x TT fp16) + bias (+resid)
// Tile 128x64, BK=64. 256 threads / 8 warps (4m x 2n); warp tile 32x32.
// Output either fp16 (Ch) or fp32+residual (Cf).
// grid (TT/64, M/128, BB)
// ---------------------------------------------------------------------------
__global__ __launch_bounds__(256)
void hgemm_kernel(const __half* __restrict__ A,
                  const __half* __restrict__ B,
                  float* __restrict__ Cf,
                  __half* __restrict__ Ch,
                  const float* __restrict__ bias,
                  const float* __restrict__ resid,
                  int M, int K)
{
    // union: tiles (sA 128x72, sB 64x72 halves) / epilogue staging (128x68 f32)
    __shared__ __align__(16) unsigned char smem_raw[34816];
    __half (*sA)[72] = (__half(*)[72])smem_raw;                  // 18432 B
    __half (*sB)[72] = (__half(*)[72])(smem_raw + 18432);        //  9216 B
    float  (*sOut)[68] = (float(*)[68])smem_raw;                 // 34816 B

    int tid  = threadIdx.x;
    int wid  = tid >> 5;
    int lane = tid & 31;
    int warp_m = wid >> 1;       // 0..3 -> 32 rows each
    int warp_n = wid & 1;        // 0..1 -> 32 cols each

    int batch = blockIdx.z;
    int n0 = blockIdx.x * 64;
    int m0 = blockIdx.y * 128;
    const __half* Bb = B + (size_t)batch * K * TT;

    float acc[2][4][4];
    #pragma unroll
    for (int mf = 0; mf < 2; mf++)
        #pragma unroll
        for (int nf = 0; nf < 4; nf++)
            #pragma unroll
            for (int j = 0; j < 4; j++) acc[mf][nf][j] = 0.f;

    for (int k0 = 0; k0 < K; k0 += 64) {
        // load A tile 128x64 (1024 uint4 chunks)
        #pragma unroll
        for (int i = 0; i < 4; i++) {
            int c = i * 256 + tid;
            int row = c >> 3, c8 = c & 7;
            *(uint4*)&sA[row][c8*8] =
                *(const uint4*)&A[(size_t)(m0 + row) * K + k0 + c8*8];
        }
        // load B tile 64x64 (512 chunks)
        #pragma unroll
        for (int i = 0; i < 2; i++) {
            int c = i * 256 + tid;
            int row = c >> 3, c8 = c & 7;
            *(uint4*)&sB[row][c8*8] =
                *(const uint4*)&Bb[(size_t)(k0 + row) * TT + n0 + c8*8];
        }
        __syncthreads();

        #pragma unroll
        for (int ks = 0; ks < 4; ks++) {
            uint32_t a[2][4], bq[2][4];
            #pragma unroll
            for (int mf = 0; mf < 2; mf++) {
                uint32_t addr = smem_u32(&sA[warp_m*32 + mf*16 + (lane & 15)]
                                            [ks*16 + (lane >> 4)*8]);
                ldsm4(a[mf], addr);
            }
            #pragma unroll
            for (int nf2 = 0; nf2 < 2; nf2++) {
                uint32_t addr = smem_u32(&sB[ks*16 + (lane & 15)]
                                            [warp_n*32 + nf2*16 + (lane >> 4)*8]);
                ldsm4t(bq[nf2], addr);
            }
            #pragma unroll
            for (int mf = 0; mf < 2; mf++) {
                #pragma unroll
                for (int nf2 = 0; nf2 < 2; nf2++) {
                    mma16816(acc[mf][nf2*2 + 0], a[mf], &bq[nf2][0]);
                    mma16816(acc[mf][nf2*2 + 1], a[mf], &bq[nf2][2]);
                }
            }
        }
        __syncthreads();
    }

    // stage to smem for coalesced output
    #pragma unroll
    for (int mf = 0; mf < 2; mf++) {
        int r0 = warp_m*32 + mf*16 + (lane >> 2);
        #pragma unroll
        for (int nf = 0; nf < 4; nf++) {
            int cc0 = warp_n*32 + nf*8 + (lane & 3)*2;
            *(float2*)&sOut[r0][cc0]     = make_float2(acc[mf][nf][0], acc[mf][nf][1]);
            *(float2*)&sOut[r0 + 8][cc0] = make_float2(acc[mf][nf][2], acc[mf][nf][3]);
        }
    }
    __syncthreads();

    #pragma unroll 4
    for (int i = 0; i < 32; i++) {
        int idx = i * 256 + tid;
        int mm = idx >> 6, nn = idx & 63;
        float v = sOut[mm][nn] + bias[m0 + mm];
        size_t go = (size_t)batch * M * TT + (size_t)(m0 + mm) * TT + n0 + nn;
        if (Ch) {
            Ch[go] = __float2half(v);
        } else {
            if (resid) v += resid[go];
            Cf[go] = v;
        }
    }
}

// ---------------------------------------------------------------------------
// HMMA flash attention. grid (TT/128, BB*NH), 256 threads / 8 warps.
// Each warp owns 16 q-rows across all 64 s-cols (no cross-warp softmax).
// Q/K/V in native (d, t) layout; P stays in registers.
// ---------------------------------------------------------------------------
__global__ __launch_bounds__(256)
void hattn_kernel()
{
    __shared__ __align__(16) __half sQ[64][136];   // (d, tq) 128 q rows
    __shared__ __align__(16) __half sK[64][72];    // (d, ts)
    __shared__ __align__(16) __half sV[64][72];    // (d, ts)
    __half (*sO)[66] = (__half(*)[66])&sQ[0][0];   // (tq, d) overlay for epilogue

    int tid  = threadIdx.x;
    int wid  = tid >> 5;
    int lane = tid & 31;

    int bh = blockIdx.y;
    int b = bh >> 3;
    int h = bh & 7;
    int qt0 = blockIdx.x * 128;

    const __half* qb = g_qkv_h + ((size_t)b*CO + (size_t)h*192) * TT;
    const __half* kb = qb + (size_t)64 * TT;
    const __half* vb = qb + (size_t)128 * TT;

    // load Q tile (64 d x 128 tq), coalesced along t
    #pragma unroll
    for (int i = 0; i < 4; i++) {
        int c = i * 256 + tid;
        int d = c >> 4, t8 = c & 15;
        *(uint4*)&sQ[d][t8*8] = *(const uint4*)&qb[(size_t)d * TT + qt0 + t8*8];
    }
    __syncthreads();

    // A-frags for S (constant over s-tiles): ldmatrix.trans from (d, tq)
    uint32_t aQ[4][4];
    #pragma unroll
    for (int ks = 0; ks < 4; ks++) {
        uint32_t r[4];
        uint32_t addr = smem_u32(&sQ[ks*16 + (lane & 15)]
                                    [wid*16 + (lane >> 4)*8]);
        ldsm4t(r, addr);
        aQ[ks][0] = r[0]; aQ[ks][1] = r[2]; aQ[ks][2] = r[1]; aQ[ks][3] = r[3];
    }

    float acc_o[8][4];
    #pragma unroll
    for (int nf = 0; nf < 8; nf++)
        #pragma unroll
        for (int j = 0; j < 4; j++) acc_o[nf][j] = 0.f;
    float m0r = -1e30f, m1r = -1e30f, l0 = 0.f, l1 = 0.f;

    for (int s0 = 0; s0 < TT; s0 += 64) {
        __syncthreads();   // prior-iter sK/sV reads complete
        #pragma unroll
        for (int i = 0; i < 2; i++) {
            int c = i * 256 + tid;
            int d = c >> 3, t8 = c & 7;
            *(uint4*)&sK[d][t8*8] = *(const uint4*)&kb[(size_t)d * TT + s0 + t8*8];
            *(uint4*)&sV[d][t8*8] = *(const uint4*)&vb[(size_t)d * TT + s0 + t8*8];
        }
        __syncthreads();

        // S = Q^T K  (16 x 64 per warp)
        float acc_s[8][4];
        #pragma unroll
        for (int nf = 0; nf < 8; nf++)
            #pragma unroll
            for (int j = 0; j < 4; j++) acc_s[nf][j] = 0.f;

        #pragma unroll
        for (int ks = 0; ks < 4; ks++) {
            #pragma unroll
            for (int nf2 = 0; nf2 < 4; nf2++) {
                uint32_t bk[4];
                uint32_t addr = smem_u32(&sK[ks*16 + (lane & 15)]
                                            [nf2*16 + (lane >> 4)*8]);
                ldsm4t(bk, addr);
                mma16816(acc_s[nf2*2 + 0], aQ[ks], &bk[0]);
                mma16816(acc_s[nf2*2 + 1], aQ[ks], &bk[2]);
            }
        }

        // scale + online softmax (rows r and r+8 per lane)
        float rm0 = -1e30f, rm1 = -1e30f;
        #pragma unroll
        for (int nf = 0; nf < 8; nf++) {
            #pragma unroll
            for (int j = 0; j < 4; j++) acc_s[nf][j] *= 0.125f;
            rm0 = fmaxf(rm0, fmaxf(acc_s[nf][0], acc_s[nf][1]));
            rm1 = fmaxf(rm1, fmaxf(acc_s[nf][2], acc_s[nf][3]));
        }
        rm0 = fmaxf(rm0, __shfl_xor_sync(0xffffffffu, rm0, 1));
        rm0 = fmaxf(rm0, __shfl_xor_sync(0xffffffffu, rm0, 2));
        rm1 = fmaxf(rm1, __shfl_xor_sync(0xffffffffu, rm1, 1));
        rm1 = fmaxf(rm1, __shfl_xor_sync(0xffffffffu, rm1, 2));

        float mn0 = fmaxf(m0r, rm0), mn1 = fmaxf(m1r, rm1);
        float corr0 = __expf(m0r - mn0), corr1 = __expf(m1r - mn1);
        m0r = mn0; m1r = mn1;

        float rs0 = 0.f, rs1 = 0.f;
        #pragma unroll
        for (int nf = 0; nf < 8; nf++) {
            acc_s[nf][0] = __expf(acc_s[nf][0] - mn0);
            acc_s[nf][1] = __expf(acc_s[nf][1] - mn0);
            acc_s[nf][2] = __expf(acc_s[nf][2] - mn1);
            acc_s[nf][3] = __expf(acc_s[nf][3] - mn1);
            rs0 += acc_s[nf][0] + acc_s[nf][1];
            rs1 += acc_s[nf][2] + acc_s[nf][3];
        }
        rs0 += __shfl_xor_sync(0xffffffffu, rs0, 1);
        rs0 += __shfl_xor_sync(0xffffffffu, rs0, 2);
        rs1 += __shfl_xor_sync(0xffffffffu, rs1, 1);
        rs1 += __shfl_xor_sync(0xffffffffu, rs1, 2);
        l0 = l0 * corr0 + rs0;
        l1 = l1 * corr1 + rs1;

        #pragma unroll
        for (int nf = 0; nf < 8; nf++) {
            acc_o[nf][0] *= corr0; acc_o[nf][1] *= corr0;
            acc_o[nf][2] *= corr1; acc_o[nf][3] *= corr1;
        }

        // P (fp16 A-frags) from S-frags: k-step ks covers s cols ks*16..+15
        uint32_t aP[4][4];
        #pragma unroll
        for (int ks = 0; ks < 4; ks++) {
            aP[ks][0] = packh2(acc_s[2*ks][0],   acc_s[2*ks][1]);
            aP[ks][1] = packh2(acc_s[2*ks][2],   acc_s[2*ks][3]);
            aP[ks][2] = packh2(acc_s[2*ks+1][0], acc_s[2*ks+1][1]);
            aP[ks][3] = packh2(acc_s[2*ks+1][2], acc_s[2*ks+1][3]);
        }

        // O += P V^T : B-frags via non-trans ldmatrix from (d, s) storage
        #pragma unroll
        for (int ks = 0; ks < 4; ks++) {
            #pragma unroll
            for (int nf2 = 0; nf2 < 4; nf2++) {
                uint32_t bv[4];
                uint32_t addr = smem_u32(&sV[nf2*16 + (lane & 7) + ((lane >> 4) << 3)]
                                            [ks*16 + ((lane >> 3) & 1)*8]);
                ldsm4(bv, addr);
                mma16816(acc_o[nf2*2 + 0], aP[ks], &bv[0]);
                mma16816(acc_o[nf2*2 + 1], aP[ks], &bv[2]);
            }
        }
    }

    // epilogue: normalize, stage (tq, d) fp16, coalesced (d-major) store
    __syncthreads();   // done with sQ (overlay)
    float inv0 = 1.0f / l0, inv1 = 1.0f / l1;
    int r0 = wid*16 + (lane >> 2);
    int r1 = r0 + 8;
    #pragma unroll
    for (int nf = 0; nf < 8; nf++) {
        int d = nf*8 + (lane & 3)*2;
        __half2 v0 = __floats2half2_rn(acc_o[nf][0]*inv0, acc_o[nf][1]*inv0);
        __half2 v1 = __floats2half2_rn(acc_o[nf][2]*inv1, acc_o[nf][3]*inv1);
        *(__half2*)&sO[r0][d] = v0;
        *(__half2*)&sO[r1][d] = v1;
    }
    __syncthreads();

    #pragma unroll 4
    for (int i = 0; i < 32; i++) {
        int idx = i * 256 + tid;
        int d = idx >> 7, tq = idx & 127;
        g_attn_h[((size_t)b*CC + h*64 + d) * TT + qt0 + tq] = sO[tq][d];
    }
}

// ---------------------------------------------------------------------------
// Launch
// ---------------------------------------------------------------------------
extern "C" void kernel_launch(void* const* d_in, const int* in_sizes, int n_in,
                              void* d_out, int out_size)
{
    const float* x        = (const float*)d_in[0];
    const float* gn_scale = (const float*)d_in[1];
    const float* gn_bias  = (const float*)d_in[2];
    const float* w_qkv    = (const float*)d_in[3];
    const float* b_qkv    = (const float*)d_in[4];
    const float* w_proj   = (const float*)d_in[5];
    const float* b_proj   = (const float*)d_in[6];
    float* out = (float*)d_out;

    __half* xn_ptr;    cudaGetSymbolAddress((void**)&xn_ptr,    g_xn_h);
    __half* qkv_ptr;   cudaGetSymbolAddress((void**)&qkv_ptr,   g_qkv_h);
    __half* attn_ptr;  cudaGetSymbolAddress((void**)&attn_ptr,  g_attn_h);
    __half* wqkv_ptr;  cudaGetSymbolAddress((void**)&wqkv_ptr,  g_wqkv_h);
    __half* wproj_ptr; cudaGetSymbolAddress((void**)&wproj_ptr, g_wproj_h);

    // 0) weight conversion to fp16
    tohalf_kernel<<<(CO*CC + 255)/256, 256>>>(w_qkv, wqkv_ptr, CO*CC);
    tohalf_kernel<<<(CC*CC + 255)/256, 256>>>(w_proj, wproj_ptr, CC*CC);

    // 1) GroupNorm (fp16 out)
    gn_kernel<<<BB*NG, 256>>>(x, gn_scale, gn_bias);

    // 2) QKV: (1536x512) @ (512x1024) per batch — HMMA, fp16 out
    {
        dim3 grid(TT/64, CO/128, BB);
        hgemm_kernel<<<grid, 256>>>(wqkv_ptr, xn_ptr, nullptr, qkv_ptr,
                                    b_qkv, nullptr, CO, CC);
    }

    // 3) Attention (HMMA flash)
    {
        dim3 grid(TT/128, BB*NH);
        hattn_kernel<<<grid, 256>>>();
    }

    // 4) Proj + bias + residual — HMMA, fp32 out
    {
        dim3 grid(TT/64, CC/128, BB);
        hgemm_kernel<<<grid, 256>>>(wproj_ptr, attn_ptr, out, nullptr,
                                    b_proj, x, CC, CC);
    }
}

// round 6
// speedup vs baseline: 11.9291x; 1.1364x over previous
#include <cuda_runtime.h>
#include <cuda_fp16.h>
#include <math.h>
#include <stdint.h>

#define BB 16
#define CC 512
#define TT 1024
#define NG 32
#define CPG 16
#define NH 8
#define DH 64
#define CO (3*CC)

// Scratch (device globals; no allocations allowed)
__device__ __half g_xn_h[(size_t)BB*CC*TT];    // groupnorm output (fp16)
__device__ __half g_qkv_h[(size_t)BB*CO*TT];   // qkv projection output (fp16)
__device__ __half g_attn_h[(size_t)BB*CC*TT];  // attention output (fp16)
__device__ __half g_wqkv_h[(size_t)CO*CC];     // fp16 weights
__device__ __half g_wproj_h[(size_t)CC*CC];

// ---------------------------------------------------------------------------
// helpers
// ---------------------------------------------------------------------------
__device__ __forceinline__ uint32_t smem_u32(const void* p) {
    return (uint32_t)__cvta_generic_to_shared(p);
}
__device__ __forceinline__ void ldsm4(uint32_t* r, uint32_t a) {
    asm volatile("ldmatrix.sync.aligned.m8n8.x4.shared.b16 {%0,%1,%2,%3}, [%4];"
                 : "=r"(r[0]), "=r"(r[1]), "=r"(r[2]), "=r"(r[3]) : "r"(a));
}
__device__ __forceinline__ void ldsm4t(uint32_t* r, uint32_t a) {
    asm volatile("ldmatrix.sync.aligned.m8n8.x4.trans.shared.b16 {%0,%1,%2,%3}, [%4];"
                 : "=r"(r[0]), "=r"(r[1]), "=r"(r[2]), "=r"(r[3]) : "r"(a));
}
__device__ __forceinline__ void mma16816(float* c, const uint32_t* a, const uint32_t* b) {
    asm volatile("mma.sync.aligned.m16n8k16.row.col.f32.f16.f16.f32 "
                 "{%0,%1,%2,%3}, {%4,%5,%6,%7}, {%8,%9}, {%0,%1,%2,%3};"
                 : "+f"(c[0]), "+f"(c[1]), "+f"(c[2]), "+f"(c[3])
                 : "r"(a[0]), "r"(a[1]), "r"(a[2]), "r"(a[3]),
                   "r"(b[0]), "r"(b[1]));
}
__device__ __forceinline__ uint32_t packh2(float x, float y) {
    __half2 h = __floats2half2_rn(x, y);
    return *(uint32_t*)&h;
}
__device__ __forceinline__ void cpa16(uint32_t dst, const void* src) {
    asm volatile("cp.async.cg.shared.global [%0], [%1], 16;" :: "r"(dst), "l"(src));
}
__device__ __forceinline__ void cpa_commit() {
    asm volatile("cp.async.commit_group;" ::: "memory");
}
__device__ __forceinline__ void cpa_wait1() {
    asm volatile("cp.async.wait_group 1;" ::: "memory");
}
__device__ __forceinline__ void cpa_wait0() {
    asm volatile("cp.async.wait_group 0;" ::: "memory");
}

// ---------------------------------------------------------------------------
// fp32 -> fp16 conversion (weights)
// ---------------------------------------------------------------------------
__global__ void tohalf_kernel(const float* __restrict__ a, __half* __restrict__ b, int n)
{
    int i = blockIdx.x * 256 + threadIdx.x;
    if (i < n) b[i] = __float2half(a[i]);
}

// ---------------------------------------------------------------------------
// GroupNorm: one block per (b, group); fp16 output.
// ---------------------------------------------------------------------------
__global__ __launch_bounds__(256)
void gn_kernel(const float* __restrict__ x,
               const float* __restrict__ scale,
               const float* __restrict__ bias)
{
    int b = blockIdx.x / NG;
    int g = blockIdx.x % NG;
    const float* xp = x + ((size_t)b*CC + (size_t)g*CPG) * TT;
    __half* yp = g_xn_h + ((size_t)b*CC + (size_t)g*CPG) * TT;
    int tid = threadIdx.x;

    float s = 0.f, ss = 0.f;
    for (int i = tid; i < CPG*TT; i += 256) {
        float v = xp[i];
        s += v; ss += v*v;
    }
    __shared__ float rs[256], rss[256];
    rs[tid] = s; rss[tid] = ss;
    __syncthreads();
    for (int o = 128; o > 0; o >>= 1) {
        if (tid < o) { rs[tid] += rs[tid+o]; rss[tid] += rss[tid+o]; }
        __syncthreads();
    }
    const float inv_n = 1.0f / (CPG*TT);
    float mean = rs[0] * inv_n;
    float var  = rss[0] * inv_n - mean*mean;
    float rstd = rsqrtf(var + 1e-5f);

    for (int i = tid; i < CPG*TT; i += 256) {
        int c = g*CPG + (i >> 10);
        yp[i] = __float2half((xp[i] - mean) * rstd * scale[c] + bias[c]);
    }
}

// ---------------------------------------------------------------------------
// HMMA GEMM v2: C[b] = A(MxK fp16, shared) @ B[b](K x TT fp16) + bias (+resid)
// CTA tile 128x128, BK=32, 2-stage cp.async double buffer.
// 256 threads / 8 warps (4m x 2n); warp tile 32x64. Direct frag epilogue.
// grid (TT/128, M/128, BB)
// ---------------------------------------------------------------------------
__global__ __launch_bounds__(256)
void hgemm_kernel(const __half* __restrict__ A,
                  const __half* __restrict__ B,
                  float* __restrict__ Cf,
                  __half* __restrict__ Ch,
                  const float* __restrict__ bias,
                  const float* __restrict__ resid,
                  int M, int K)
{
    __shared__ __align__(16) __half sA[2][128][40];   // 20480 B
    __shared__ __align__(16) __half sB[2][32][136];   // 17408 B

    int tid  = threadIdx.x;
    int wid  = tid >> 5;
    int lane = tid & 31;
    int warp_m = wid & 3;        // 0..3 -> 32 rows each
    int warp_n = wid >> 2;       // 0..1 -> 64 cols each

    int batch = blockIdx.z;
    int n0 = blockIdx.x * 128;
    int m0 = blockIdx.y * 128;
    const __half* Bb = B + (size_t)batch * K * TT;

    // load mappings (2 chunks each for A and B per stage)
    int a_row0 = tid >> 2,        a_col = (tid & 3) * 8;        // chunks 0..255
    int b_row0 = tid >> 4,        b_col = (tid & 15) * 8;

    float acc[2][8][4];
    #pragma unroll
    for (int mf = 0; mf < 2; mf++)
        #pragma unroll
        for (int nf = 0; nf < 8; nf++)
            #pragma unroll
            for (int j = 0; j < 4; j++) acc[mf][nf][j] = 0.f;

    const int nk = K / 32;

    // prologue: stage 0
    {
        int k0 = 0;
        #pragma unroll
        for (int i = 0; i < 2; i++) {
            int row = a_row0 + i * 64;
            cpa16(smem_u32(&sA[0][row][a_col]), &A[(size_t)(m0 + row) * K + k0 + a_col]);
        }
        #pragma unroll
        for (int i = 0; i < 2; i++) {
            int row = b_row0 + i * 16;
            cpa16(smem_u32(&sB[0][row][b_col]), &Bb[(size_t)(k0 + row) * TT + n0 + b_col]);
        }
        cpa_commit();
    }

    for (int kc = 0; kc < nk; kc++) {
        if (kc + 1 < nk) {
            int st = (kc + 1) & 1;
            int k0 = (kc + 1) * 32;
            #pragma unroll
            for (int i = 0; i < 2; i++) {
                int row = a_row0 + i * 64;
                cpa16(smem_u32(&sA[st][row][a_col]), &A[(size_t)(m0 + row) * K + k0 + a_col]);
            }
            #pragma unroll
            for (int i = 0; i < 2; i++) {
                int row = b_row0 + i * 16;
                cpa16(smem_u32(&sB[st][row][b_col]), &Bb[(size_t)(k0 + row) * TT + n0 + b_col]);
            }
            cpa_commit();
            cpa_wait1();
        } else {
            cpa_wait0();
        }
        __syncthreads();

        int st = kc & 1;
        #pragma unroll
        for (int ks = 0; ks < 2; ks++) {
            uint32_t a[2][4], bq[4][4];
            #pragma unroll
            for (int mf = 0; mf < 2; mf++) {
                uint32_t addr = smem_u32(&sA[st][warp_m*32 + mf*16 + (lane & 15)]
                                             [ks*16 + (lane >> 4)*8]);
                ldsm4(a[mf], addr);
            }
            #pragma unroll
            for (int nf2 = 0; nf2 < 4; nf2++) {
                uint32_t addr = smem_u32(&sB[st][ks*16 + (lane & 15)]
                                             [warp_n*64 + nf2*16 + (lane >> 4)*8]);
                ldsm4t(bq[nf2], addr);
            }
            #pragma unroll
            for (int mf = 0; mf < 2; mf++) {
                #pragma unroll
                for (int nf2 = 0; nf2 < 4; nf2++) {
                    mma16816(acc[mf][nf2*2 + 0], a[mf], &bq[nf2][0]);
                    mma16816(acc[mf][nf2*2 + 1], a[mf], &bq[nf2][2]);
                }
            }
        }
        __syncthreads();
    }

    // direct epilogue from fragments
    #pragma unroll
    for (int mf = 0; mf < 2; mf++) {
        int r = m0 + warp_m*32 + mf*16 + (lane >> 2);
        float bv0 = bias[r], bv1 = bias[r + 8];
        #pragma unroll
        for (int nf = 0; nf < 8; nf++) {
            int cc = n0 + warp_n*64 + nf*8 + (lane & 3)*2;
            size_t go0 = (size_t)batch * M * TT + (size_t)r * TT + cc;
            size_t go1 = go0 + (size_t)8 * TT;
            if (Ch) {
                *(__half2*)&Ch[go0] = __floats2half2_rn(acc[mf][nf][0] + bv0,
                                                        acc[mf][nf][1] + bv0);
                *(__half2*)&Ch[go1] = __floats2half2_rn(acc[mf][nf][2] + bv1,
                                                        acc[mf][nf][3] + bv1);
            } else {
                float2 v0 = make_float2(acc[mf][nf][0] + bv0, acc[mf][nf][1] + bv0);
                float2 v1 = make_float2(acc[mf][nf][2] + bv1, acc[mf][nf][3] + bv1);
                if (resid) {
                    float2 r0 = *(const float2*)&resid[go0];
                    float2 r1 = *(const float2*)&resid[go1];
                    v0.x += r0.x; v0.y += r0.y;
                    v1.x += r1.x; v1.y += r1.y;
                }
                *(float2*)&Cf[go0] = v0;
                *(float2*)&Cf[go1] = v1;
            }
        }
    }
}

// ---------------------------------------------------------------------------
// HMMA flash attention v2: cp.async double-buffered K/V tiles.
// grid (TT/128, BB*NH), 256 threads / 8 warps; warp owns 16 q-rows x 64 s.
// ---------------------------------------------------------------------------
__global__ __launch_bounds__(256)
void hattn_kernel()
{
    __shared__ __align__(16) __half sQ[64][136];      // (d, tq)
    __shared__ __align__(16) __half sK[2][64][72];    // (d, ts) x2
    __shared__ __align__(16) __half sV[2][64][72];    // (d, ts) x2
    __half (*sO)[66] = (__half(*)[66])&sQ[0][0];      // (tq, d) overlay

    int tid  = threadIdx.x;
    int wid  = tid >> 5;
    int lane = tid & 31;

    int bh = blockIdx.y;
    int b = bh >> 3;
    int h = bh & 7;
    int qt0 = blockIdx.x * 128;

    const __half* qb = g_qkv_h + ((size_t)b*CO + (size_t)h*192) * TT;
    const __half* kb = qb + (size_t)64 * TT;
    const __half* vb = qb + (size_t)128 * TT;

    // K/V tile load mapping (cp.async): 512 chunks each -> 2 per thread each
    int kv_row0 = tid >> 3;           // chunk row (8 chunks per 64-half row)
    int kv_col  = (tid & 7) * 8;

    // prologue: s-tile 0 into buffer 0
    #pragma unroll
    for (int i = 0; i < 2; i++) {
        int d = kv_row0 + i * 32;
        cpa16(smem_u32(&sK[0][d][kv_col]), &kb[(size_t)d * TT + 0 + kv_col]);
        cpa16(smem_u32(&sV[0][d][kv_col]), &vb[(size_t)d * TT + 0 + kv_col]);
    }
    cpa_commit();

    // load Q tile (64 d x 128 tq)
    #pragma unroll
    for (int i = 0; i < 4; i++) {
        int c = i * 256 + tid;
        int d = c >> 4, t8 = c & 15;
        *(uint4*)&sQ[d][t8*8] = *(const uint4*)&qb[(size_t)d * TT + qt0 + t8*8];
    }
    __syncthreads();

    // A-frags for S (constant over s-tiles): ldmatrix.trans from (d, tq)
    uint32_t aQ[4][4];
    #pragma unroll
    for (int ks = 0; ks < 4; ks++) {
        uint32_t r[4];
        uint32_t addr = smem_u32(&sQ[ks*16 + (lane & 15)]
                                    [wid*16 + (lane >> 4)*8]);
        ldsm4t(r, addr);
        aQ[ks][0] = r[0]; aQ[ks][1] = r[2]; aQ[ks][2] = r[1]; aQ[ks][3] = r[3];
    }

    float acc_o[8][4];
    #pragma unroll
    for (int nf = 0; nf < 8; nf++)
        #pragma unroll
        for (int j = 0; j < 4; j++) acc_o[nf][j] = 0.f;
    float m0r = -1e30f, m1r = -1e30f, l0 = 0.f, l1 = 0.f;

    const int nt = TT / 64;
    for (int sidx = 0; sidx < nt; sidx++) {
        if (sidx + 1 < nt) {
            int st = (sidx + 1) & 1;
            int s0 = (sidx + 1) * 64;
            #pragma unroll
            for (int i = 0; i < 2; i++) {
                int d = kv_row0 + i * 32;
                cpa16(smem_u32(&sK[st][d][kv_col]), &kb[(size_t)d * TT + s0 + kv_col]);
                cpa16(smem_u32(&sV[st][d][kv_col]), &vb[(size_t)d * TT + s0 + kv_col]);
            }
            cpa_commit();
            cpa_wait1();
        } else {
            cpa_wait0();
        }
        __syncthreads();

        int st = sidx & 1;

        // S = Q^T K  (16 x 64 per warp)
        float acc_s[8][4];
        #pragma unroll
        for (int nf = 0; nf < 8; nf++)
            #pragma unroll
            for (int j = 0; j < 4; j++) acc_s[nf][j] = 0.f;

        #pragma unroll
        for (int ks = 0; ks < 4; ks++) {
            #pragma unroll
            for (int nf2 = 0; nf2 < 4; nf2++) {
                uint32_t bk[4];
                uint32_t addr = smem_u32(&sK[st][ks*16 + (lane & 15)]
                                             [nf2*16 + (lane >> 4)*8]);
                ldsm4t(bk, addr);
                mma16816(acc_s[nf2*2 + 0], aQ[ks], &bk[0]);
                mma16816(acc_s[nf2*2 + 1], aQ[ks], &bk[2]);
            }
        }

        // scale + online softmax (rows r and r+8 per lane)
        float rm0 = -1e30f, rm1 = -1e30f;
        #pragma unroll
        for (int nf = 0; nf < 8; nf++) {
            #pragma unroll
            for (int j = 0; j < 4; j++) acc_s[nf][j] *= 0.125f;
            rm0 = fmaxf(rm0, fmaxf(acc_s[nf][0], acc_s[nf][1]));
            rm1 = fmaxf(rm1, fmaxf(acc_s[nf][2], acc_s[nf][3]));
        }
        rm0 = fmaxf(rm0, __shfl_xor_sync(0xffffffffu, rm0, 1));
        rm0 = fmaxf(rm0, __shfl_xor_sync(0xffffffffu, rm0, 2));
        rm1 = fmaxf(rm1, __shfl_xor_sync(0xffffffffu, rm1, 1));
        rm1 = fmaxf(rm1, __shfl_xor_sync(0xffffffffu, rm1, 2));

        float mn0 = fmaxf(m0r, rm0), mn1 = fmaxf(m1r, rm1);
        float corr0 = __expf(m0r - mn0), corr1 = __expf(m1r - mn1);
        m0r = mn0; m1r = mn1;

        float rs0 = 0.f, rs1 = 0.f;
        #pragma unroll
        for (int nf = 0; nf < 8; nf++) {
            acc_s[nf][0] = __expf(acc_s[nf][0] - mn0);
            acc_s[nf][1] = __expf(acc_s[nf][1] - mn0);
            acc_s[nf][2] = __expf(acc_s[nf][2] - mn1);
            acc_s[nf][3] = __expf(acc_s[nf][3] - mn1);
            rs0 += acc_s[nf][0] + acc_s[nf][1];
            rs1 += acc_s[nf][2] + acc_s[nf][3];
        }
        rs0 += __shfl_xor_sync(0xffffffffu, rs0, 1);
        rs0 += __shfl_xor_sync(0xffffffffu, rs0, 2);
        rs1 += __shfl_xor_sync(0xffffffffu, rs1, 1);
        rs1 += __shfl_xor_sync(0xffffffffu, rs1, 2);
        l0 = l0 * corr0 + rs0;
        l1 = l1 * corr1 + rs1;

        #pragma unroll
        for (int nf = 0; nf < 8; nf++) {
            acc_o[nf][0] *= corr0; acc_o[nf][1] *= corr0;
            acc_o[nf][2] *= corr1; acc_o[nf][3] *= corr1;
        }

        // P (fp16 A-frags) from S-frags
        uint32_t aP[4][4];
        #pragma unroll
        for (int ks = 0; ks < 4; ks++) {
            aP[ks][0] = packh2(acc_s[2*ks][0],   acc_s[2*ks][1]);
            aP[ks][1] = packh2(acc_s[2*ks][2],   acc_s[2*ks][3]);
            aP[ks][2] = packh2(acc_s[2*ks+1][0], acc_s[2*ks+1][1]);
            aP[ks][3] = packh2(acc_s[2*ks+1][2], acc_s[2*ks+1][3]);
        }

        // O += P V^T : B-frags via non-trans ldmatrix from (d, s) storage
        #pragma unroll
        for (int ks = 0; ks < 4; ks++) {
            #pragma unroll
            for (int nf2 = 0; nf2 < 4; nf2++) {
                uint32_t bv[4];
                uint32_t addr = smem_u32(&sV[st][nf2*16 + (lane & 7) + ((lane >> 4) << 3)]
                                             [ks*16 + ((lane >> 3) & 1)*8]);
                ldsm4(bv, addr);
                mma16816(acc_o[nf2*2 + 0], aP[ks], &bv[0]);
                mma16816(acc_o[nf2*2 + 1], aP[ks], &bv[2]);
            }
        }
        __syncthreads();
    }

    // epilogue: normalize, stage (tq, d) fp16, coalesced (d-major) store
    float inv0 = 1.0f / l0, inv1 = 1.0f / l1;
    int r0 = wid*16 + (lane >> 2);
    int r1 = r0 + 8;
    #pragma unroll
    for (int nf = 0; nf < 8; nf++) {
        int d = nf*8 + (lane & 3)*2;
        __half2 v0 = __floats2half2_rn(acc_o[nf][0]*inv0, acc_o[nf][1]*inv0);
        __half2 v1 = __floats2half2_rn(acc_o[nf][2]*inv1, acc_o[nf][3]*inv1);
        *(__half2*)&sO[r0][d] = v0;
        *(__half2*)&sO[r1][d] = v1;
    }
    __syncthreads();

    #pragma unroll 4
    for (int i = 0; i < 32; i++) {
        int idx = i * 256 + tid;
        int d = idx >> 7, tq = idx & 127;
        g_attn_h[((size_t)b*CC + h*64 + d) * TT + qt0 + tq] = sO[tq][d];
    }
}

// ---------------------------------------------------------------------------
// Launch
// ---------------------------------------------------------------------------
extern "C" void kernel_launch(void* const* d_in, const int* in_sizes, int n_in,
                              void* d_out, int out_size)
{
    const float* x        = (const float*)d_in[0];
    const float* gn_scale = (const float*)d_in[1];
    const float* gn_bias  = (const float*)d_in[2];
    const float* w_qkv    = (const float*)d_in[3];
    const float* b_qkv    = (const float*)d_in[4];
    const float* w_proj   = (const float*)d_in[5];
    const float* b_proj   = (const float*)d_in[6];
    float* out = (float*)d_out;

    __half* xn_ptr;    cudaGetSymbolAddress((void**)&xn_ptr,    g_xn_h);
    __half* qkv_ptr;   cudaGetSymbolAddress((void**)&qkv_ptr,   g_qkv_h);
    __half* attn_ptr;  cudaGetSymbolAddress((void**)&attn_ptr,  g_attn_h);
    __half* wqkv_ptr;  cudaGetSymbolAddress((void**)&wqkv_ptr,  g_wqkv_h);
    __half* wproj_ptr; cudaGetSymbolAddress((void**)&wproj_ptr, g_wproj_h);

    // 0) weight conversion to fp16
    tohalf_kernel<<<(CO*CC + 255)/256, 256>>>(w_qkv, wqkv_ptr, CO*CC);
    tohalf_kernel<<<(CC*CC + 255)/256, 256>>>(w_proj, wproj_ptr, CC*CC);

    // 1) GroupNorm (fp16 out)
    gn_kernel<<<BB*NG, 256>>>(x, gn_scale, gn_bias);

    // 2) QKV: (1536x512) @ (512x1024) per batch — HMMA, fp16 out
    {
        dim3 grid(TT/128, CO/128, BB);
        hgemm_kernel<<<grid, 256>>>(wqkv_ptr, xn_ptr, nullptr, qkv_ptr,
                                    b_qkv, nullptr, CO, CC);
    }

    // 3) Attention (HMMA flash, double-buffered)
    {
        dim3 grid(TT/128, BB*NH);
        hattn_kernel<<<grid, 256>>>();
    }

    // 4) Proj + bias + residual — HMMA, fp32 out
    {
        dim3 grid(TT/128, CC/128, BB);
        hgemm_kernel<<<grid, 256>>>(wproj_ptr, attn_ptr, out, nullptr,
                                    b_proj, x, CC, CC);
    }
}